// round 11
// baseline (speedup 1.0000x reference)
#include <cuda_runtime.h>
#include <cuda_bf16.h>
#include <math.h>

// Problem constants (GaussianDPMM): N=262144, K=128, D=64
#define DDIM 64
#define KDIM 128
#define ROWS_PER_BLOCK 128
#define THREADS 256

// Smem layout (floats)
#define XS_STRIDE 68                 // 64 + 4 pad: avoids bank conflicts, keeps 16B align
#define XS_FLOATS (ROWS_PER_BLOCK * XS_STRIDE)        // 8704
#define COEF_FLOATS (DDIM * (KDIM/2) * 2)             // 8192 (float2 per k-pair)
#define SMEM_FLOATS (2*XS_FLOATS + 2*COEF_FLOATS + KDIM)
#define SMEM_BYTES (SMEM_FLOATS * 4)                   // 135680

// Precomputed per-cluster data (written by prep kernel, read by main kernel)
__device__ float g_w[COEF_FLOATS];    // [d][kpair].{k0,k1} : tau*nb
__device__ float g_nb[COEF_FLOATS];   // [d][kpair].{k0,k1} : n/B
__device__ float g_cst[KDIM];         // per-k additive constant
__device__ double g_kl;               // total KL
__device__ double g_bsum[8192];       // per-block sum of log_norm

// ---------------------------------------------------------------------------
// double-precision digamma (x > 0), accurate to ~1e-14 for our argument range
// ---------------------------------------------------------------------------
__device__ __forceinline__ double digamma_d(double x) {
    double r = 0.0;
    while (x < 6.0) { r -= 1.0 / x; x += 1.0; }
    double f = 1.0 / (x * x);
    double s = f * (1.0/12.0 - f * (1.0/120.0 - f * (1.0/252.0 - f * (1.0/240.0
               - f * (1.0/132.0 - f * (691.0/32760.0))))));
    return r + log(x) - 0.5 / x - s;
}

// ---------------------------------------------------------------------------
// Kernel 1: per-cluster precompute + KL terms.  1 block, K threads.
// ---------------------------------------------------------------------------
__global__ void dpmm_prep(const float* __restrict__ nat_u,
                          const float* __restrict__ nat_v,
                          const float* __restrict__ nat_tau,
                          const float* __restrict__ nat_c,
                          const float* __restrict__ nat_n,
                          const float* __restrict__ nat_B) {
    const int k = threadIdx.x;   // 0..127
    __shared__ double elm[KDIM];
    __shared__ double red[KDIM];

    const double Dn = (double)DDIM;
    const double ALPHA_DP = 1.0, TAU0 = 0.0, C0 = 1.0, B0 = 1.0;
    const double N0 = Dn + 2.0;
    const double a0g = 0.5 * N0, b0g = 0.5 * B0;

    double u = (double)nat_u[k] + 1.0;
    double v = (double)nat_v[k] + 1.0;
    double c = (double)nat_c[k];
    double n = (double)nat_n[k] - Dn - 2.0;

    double dgu = digamma_d(u), dgv = digamma_d(v), dguv = digamma_d(u + v);
    double els = dgu - dguv;
    elm[k] = dgv - dguv;

    double a1 = 0.5 * n;
    double dga1 = digamma_d(a1);
    double eld = Dn * dga1;           // E[log|Lambda|] accumulator
    double lga1 = lgamma(a1), lga0 = lgamma(a0g);

    double sumt = 0.0, klg = 0.0, kln = 0.0;
    const int kp = k >> 1, comp = k & 1;
    for (int d = 0; d < DDIM; ++d) {
        double tau = (double)nat_tau[k * DDIM + d] / c;
        double B   = (double)nat_B[k * DDIM + d] - c * tau * tau;
        double nb  = n / B;
        double w   = tau * nb;
        eld  -= log(0.5 * B);
        sumt += tau * tau * nb;
        g_w [(d * (KDIM/2) + kp) * 2 + comp] = (float)w;
        g_nb[(d * (KDIM/2) + kp) * 2 + comp] = (float)nb;
        double b1 = 0.5 * B;
        klg += (a1 - a0g) * dga1 - lga1 + lga0
             + a0g * (log(b1) - log(b0g)) + a1 * (b0g - b1) / b1;
        double dt = tau - TAU0;
        kln += log(c / C0) + C0 / c - 1.0 + C0 * nb * dt * dt;
    }
    kln *= 0.5;

    // KL Beta(u,v) || Beta(1, alphaDP)
    double a0 = 1.0, b0 = ALPHA_DP;
    double klb = lgamma(u + v) - lgamma(u) - lgamma(v)
               - (lgamma(a0 + b0) - lgamma(a0) - lgamma(b0))
               + (u - a0) * dgu + (v - b0) * dgv
               + (a0 + b0 - u - v) * dguv;

    __syncthreads();
    double pre = 0.0;
    for (int j = 0; j < k; ++j) pre += elm[j];   // cumsum(e_log_1m) exclusive

    const double LOG2PI = 1.8378770664093454836;
    double cst = els + pre + 0.5 * (eld - Dn * LOG2PI - sumt - Dn / c);
    g_cst[k] = (float)cst;

    red[k] = klb + klg + kln;
    __syncthreads();
    for (int t = KDIM / 2; t > 0; t >>= 1) {
        if (k < t) red[k] += red[k + t];
        __syncthreads();
    }
    if (k == 0) g_kl = red[0];
}

// ---------------------------------------------------------------------------
// f32x2 packed helpers
// ---------------------------------------------------------------------------
__device__ __forceinline__ unsigned long long pack2(float f) {
    unsigned long long r;
    unsigned u = __float_as_uint(f);
    asm("mov.b64 %0, {%1, %1};" : "=l"(r) : "r"(u));
    return r;
}
__device__ __forceinline__ void fma2(unsigned long long& d,
                                     unsigned long long a, unsigned long long b) {
    asm("fma.rn.f32x2 %0, %1, %2, %0;" : "+l"(d) : "l"(a), "l"(b));
}

// ---------------------------------------------------------------------------
// Kernel 2: fused GEMM + softmax.  Block = 256 thr, tile = 128 rows x 128 k.
// Thread (tx = tid&15 -> k dim, ty = tid>>4 -> row dim) owns 8 rows x 4 kpairs.
// rows: i*16 + ty (i=0..7).  kpairs: j*16 + tx (j=0..3) -> k = 2*kp, 2*kp+1.
// ---------------------------------------------------------------------------
__global__ void __launch_bounds__(THREADS, 1)
dpmm_main(const float* __restrict__ x, float* __restrict__ out) {
    extern __shared__ float sm[];
    float* Xs  = sm;                       // [128][68]
    float* Hs  = sm + XS_FLOATS;           // [128][68]  (-0.5*x^2)
    float* Wp  = sm + 2 * XS_FLOATS;       // [64][64] float2
    float* Np  = Wp + COEF_FLOATS;         // [64][64] float2
    float* Cst = Np + COEF_FLOATS;         // [128]

    const int tid = threadIdx.x;
    const int tx = tid & 15, ty = tid >> 4;
    const int row0 = blockIdx.x * ROWS_PER_BLOCK;

    // stage coefficients (L2 resident across blocks)
    for (int i = tid; i < COEF_FLOATS / 4; i += THREADS) {
        ((float4*)Wp)[i] = ((const float4*)g_w)[i];
        ((float4*)Np)[i] = ((const float4*)g_nb)[i];
    }
    if (tid < KDIM) Cst[tid] = g_cst[tid];

    // stage x rows + h = -0.5*x^2
    for (int i = tid; i < ROWS_PER_BLOCK * (DDIM / 4); i += THREADS) {
        int rr = i >> 4, cc = i & 15;
        float4 xv = *(const float4*)&x[(size_t)(row0 + rr) * DDIM + cc * 4];
        *(float4*)&Xs[rr * XS_STRIDE + cc * 4] = xv;
        float4 hv;
        hv.x = -0.5f * xv.x * xv.x;  hv.y = -0.5f * xv.y * xv.y;
        hv.z = -0.5f * xv.z * xv.z;  hv.w = -0.5f * xv.w * xv.w;
        *(float4*)&Hs[rr * XS_STRIDE + cc * 4] = hv;
    }
    __syncthreads();

    unsigned long long acc[8][4];
#pragma unroll
    for (int i = 0; i < 8; ++i)
#pragma unroll
        for (int j = 0; j < 4; ++j) acc[i][j] = 0ULL;

#pragma unroll 1
    for (int d4 = 0; d4 < DDIM / 4; ++d4) {
        float xv[8][4], hv[8][4];
#pragma unroll
        for (int i = 0; i < 8; ++i) {
            int r = i * 16 + ty;
            *(float4*)xv[i] = *(const float4*)&Xs[r * XS_STRIDE + d4 * 4];
            *(float4*)hv[i] = *(const float4*)&Hs[r * XS_STRIDE + d4 * 4];
        }
#pragma unroll
        for (int dd = 0; dd < 4; ++dd) {
            unsigned long long wv[4], nv[4];
            const int dbase = (d4 * 4 + dd) * (KDIM / 2);
#pragma unroll
            for (int j = 0; j < 4; ++j) {
                wv[j] = *(const unsigned long long*)&Wp[(dbase + j * 16 + tx) * 2];
                nv[j] = *(const unsigned long long*)&Np[(dbase + j * 16 + tx) * 2];
            }
#pragma unroll
            for (int i = 0; i < 8; ++i) {
                unsigned long long xx = pack2(xv[i][dd]);
                unsigned long long hh = pack2(hv[i][dd]);
#pragma unroll
                for (int j = 0; j < 4; ++j) {
                    fma2(acc[i][j], wv[j], xx);
                    fma2(acc[i][j], nv[j], hh);
                }
            }
        }
    }

    // Epilogue: softmax over k (row spans lanes 0..15 / 16..31 of warp)
    double lls = 0.0;
#pragma unroll
    for (int i = 0; i < 8; ++i) {
        float lr[8];
#pragma unroll
        for (int j = 0; j < 4; ++j) {
            int k0 = (j * 16 + tx) * 2;
            lr[2*j]   = __uint_as_float((unsigned)(acc[i][j]))        + Cst[k0];
            lr[2*j+1] = __uint_as_float((unsigned)(acc[i][j] >> 32))  + Cst[k0 + 1];
        }
        float m = lr[0];
#pragma unroll
        for (int t = 1; t < 8; ++t) m = fmaxf(m, lr[t]);
#pragma unroll
        for (int o = 1; o < 16; o <<= 1)
            m = fmaxf(m, __shfl_xor_sync(0xffffffffu, m, o));
        float e[8], s = 0.0f;
#pragma unroll
        for (int t = 0; t < 8; ++t) { e[t] = __expf(lr[t] - m); s += e[t]; }
#pragma unroll
        for (int o = 1; o < 16; o <<= 1)
            s += __shfl_xor_sync(0xffffffffu, s, o);
        float inv = 1.0f / s;
        size_t row = (size_t)row0 + i * 16 + ty;
        float* ro = out + row * KDIM;
#pragma unroll
        for (int j = 0; j < 4; ++j) {
            int k0 = (j * 16 + tx) * 2;
            *(float2*)&ro[k0] = make_float2(e[2*j] * inv, e[2*j+1] * inv);
        }
        if (tx == 0) lls += (double)m + (double)logf(s);
    }

    // deterministic per-block reduction of sum(log_norm)
    __syncthreads();
    double* rb = (double*)sm;
    rb[tid] = lls;
    __syncthreads();
    for (int t = THREADS / 2; t > 0; t >>= 1) {
        if (tid < t) rb[tid] += rb[tid + t];
        __syncthreads();
    }
    if (tid == 0) g_bsum[blockIdx.x] = rb[0];
}

// ---------------------------------------------------------------------------
// Kernel 3: deterministic final reduction; writes -elbo = KL - ll
// ---------------------------------------------------------------------------
__global__ void dpmm_finalize(float* __restrict__ out, int nblocks, long long scalar_idx) {
    __shared__ double rsm[256];
    double s = 0.0;
    for (int i = threadIdx.x; i < nblocks; i += 256) s += g_bsum[i];
    rsm[threadIdx.x] = s;
    __syncthreads();
    for (int t = 128; t > 0; t >>= 1) {
        if (threadIdx.x < t) rsm[threadIdx.x] += rsm[threadIdx.x + t];
        __syncthreads();
    }
    if (threadIdx.x == 0) out[scalar_idx] = (float)(g_kl - rsm[0]);
}

// ---------------------------------------------------------------------------
extern "C" void kernel_launch(void* const* d_in, const int* in_sizes, int n_in,
                              void* d_out, int out_size) {
    const float* x       = (const float*)d_in[0];
    const float* nat_u   = (const float*)d_in[1];
    const float* nat_v   = (const float*)d_in[2];
    const float* nat_tau = (const float*)d_in[3];
    const float* nat_c   = (const float*)d_in[4];
    const float* nat_n   = (const float*)d_in[5];
    const float* nat_B   = (const float*)d_in[6];
    float* out = (float*)d_out;

    const int N = in_sizes[0] / DDIM;
    const int nblocks = N / ROWS_PER_BLOCK;

    static int attr_done = 0;
    cudaFuncSetAttribute(dpmm_main, cudaFuncAttributeMaxDynamicSharedMemorySize,
                         SMEM_BYTES);
    (void)attr_done;

    dpmm_prep<<<1, KDIM>>>(nat_u, nat_v, nat_tau, nat_c, nat_n, nat_B);
    dpmm_main<<<nblocks, THREADS, SMEM_BYTES>>>(x, out);
    dpmm_finalize<<<1, 256>>>(out, nblocks, (long long)out_size - 1);
}